// round 7
// baseline (speedup 1.0000x reference)
#include <cuda_runtime.h>
#include <math.h>
#include <stdint.h>

#define BATCH 8
#define CHN 128
#define HH 56
#define WW 56
#define TILE_PTS 128
#define NTHREADS 256
#define NTILES 4096
#define GRID_CTAS 148

#define A_STRIDE 260     // 65 x 16B rows: %8==1 -> conflict-free LDSM
#define W1_STRIDE 260
#define WST 68           // staging stride for W2/W3 (%8==4, conflict-free)

// float-index offsets in dynamic smem
#define FOFF_A     0                          // 128 x 260
#define FOFF_W1    (128 * A_STRIDE)           // 64 x 260
#define FOFF_MISC  (FOFF_W1 + 64 * W1_STRIDE)
#define MI_B1   0
#define MI_B2   64
#define MI_B3   128
#define MI_W4   192
#define MI_BG   256      // 192 floats
#define MI_FX   448
#define MI_FY   576
#define MI_VA   704
#define MI_X0   832
#define MI_Y0   960
#define MI_PX   1088
#define MI_PY   1216
#define MI_PZ   1344
#define MI_PART 1472     // 256 floats
#define SMEM_TOTAL ((FOFF_MISC + 1792) * 4)   // 206,848 bytes

// ---------------- globals ----------------
__device__ float g_tf[BATCH * HH * WW * CHN];   // (B,H,W,C) features
__device__ float g_W1T[64 * W1_STRIDE];         // n-major padded tf32 image
__device__ float g_W2Tc[64 * 64];               // compact n-major tf32
__device__ float g_W3Tc[64 * 64];

__device__ __forceinline__ float to_tf32(float x) {
    uint32_t r;
    asm("cvt.rna.tf32.f32 %0, %1;" : "=r"(r) : "f"(x));
    return __uint_as_float(r);
}
__device__ __forceinline__ uint32_t smem_u32(const void* p) {
    uint32_t a;
    asm("{ .reg .u64 t; cvta.to.shared.u64 t, %1; cvt.u32.u64 %0, t; }" : "=r"(a) : "l"(p));
    return a;
}
__device__ __forceinline__ void ldsm4(uint32_t* r, uint32_t addr) {
    asm volatile("ldmatrix.sync.aligned.m8n8.x4.shared.b16 {%0,%1,%2,%3}, [%4];"
                 : "=r"(r[0]), "=r"(r[1]), "=r"(r[2]), "=r"(r[3]) : "r"(addr));
}
__device__ __forceinline__ void mma16n8k8(float* d, const uint32_t* a, uint32_t b0, uint32_t b1) {
    asm volatile(
        "mma.sync.aligned.m16n8k8.row.col.f32.tf32.tf32.f32 "
        "{%0,%1,%2,%3}, {%4,%5,%6,%7}, {%8,%9}, {%0,%1,%2,%3};"
        : "+f"(d[0]), "+f"(d[1]), "+f"(d[2]), "+f"(d[3])
        : "r"(a[0]), "r"(a[1]), "r"(a[2]), "r"(a[3]), "r"(b0), "r"(b1));
}

// sin(2*pi*ph), cos(2*pi*ph) on the FMA pipe (no MUFU).
// Reduce in turns: n = rint(2*ph), r = ph - n/2 => 2*pi*r in [-pi/2, pi/2];
// Taylor deg-9 (sin) / deg-10 (cos); parity of n flips both signs.
__device__ __forceinline__ void sincos_2pi_fast(float ph, float& s, float& c) {
    const float n = rintf(ph + ph);
    const float r = fmaf(-0.5f, n, ph);
    const float x = 6.2831853071795865f * r;
    const float u = x * x;
    float sp = fmaf(u, 2.7557319e-6f, -1.9841270e-4f);
    sp = fmaf(u, sp, 8.3333333e-3f);
    sp = fmaf(u, sp, -0.16666667f);
    sp = fmaf(u, sp, 1.0f);
    const float ss = x * sp;
    float cp = fmaf(u, -2.7557319e-7f, 2.4801587e-5f);
    cp = fmaf(u, cp, -1.3888889e-3f);
    cp = fmaf(u, cp, 4.1666667e-2f);
    cp = fmaf(u, cp, -0.5f);
    cp = fmaf(u, cp, 1.0f);
    const int i = (int)n;
    const uint32_t sb = ((uint32_t)i & 1u) << 31;
    s = __uint_as_float(__float_as_uint(ss) ^ sb);
    c = __uint_as_float(__float_as_uint(cp) ^ sb);
}

// ---------------------------------------------------------------------------
// Kernel 1: transpose features + prep weight images (merged)
// ---------------------------------------------------------------------------
__global__ void transpose_kernel(const float* __restrict__ f,
                                 const float* __restrict__ W1,
                                 const float* __restrict__ W2,
                                 const float* __restrict__ W3) {
    __shared__ float tile[32][33];
    const int b  = blockIdx.z;
    const int c0 = blockIdx.y << 5;
    const int s0 = blockIdx.x << 5;
    const int tx = threadIdx.x, ty = threadIdx.y;
    tile[ty][tx] = f[(size_t)(b * CHN + c0 + ty) * 3136 + (s0 + tx)];
    __syncthreads();
    g_tf[(size_t)(b * 3136 + s0 + ty) * CHN + (c0 + tx)] = tile[tx][ty];

    if (blockIdx.x == 0 && blockIdx.y == 0) {
        const int t = ty * 32 + tx;
        const int base = b * 1024 + t;
        for (int i = base; i < 64 * 256; i += 8192) {
            int n = i & 63, k = i >> 6;
            g_W1T[n * W1_STRIDE + k] = to_tf32(W1[k * 64 + n]);
        }
        for (int i = base; i < 64 * 64; i += 8192) {
            int n = i & 63, k = i >> 6;
            g_W2Tc[n * 64 + k] = to_tf32(W2[k * 64 + n]);
            g_W3Tc[n * 64 + k] = to_tf32(W3[k * 64 + n]);
        }
    }
}

// ---------------------------------------------------------------------------
// Kernel 2: persistent fused decoder
// ---------------------------------------------------------------------------
__global__ __launch_bounds__(NTHREADS, 1)
void decoder_kernel(const float* __restrict__ points,
                    const float* __restrict__ kmat,
                    const float* __restrict__ rtm,
                    const float* __restrict__ Bg,
                    const float* __restrict__ b1,
                    const float* __restrict__ b2,
                    const float* __restrict__ b3,
                    const float* __restrict__ W4,
                    const float* __restrict__ b4,
                    float* __restrict__ out) {
    extern __shared__ float sm[];
    float* sA  = sm + FOFF_A;
    float* sW1 = sm + FOFF_W1;
    float* sMi = sm + FOFF_MISC;
    float* sB1 = sMi + MI_B1;
    float* sB2 = sMi + MI_B2;
    float* sB3 = sMi + MI_B3;
    float* sW4 = sMi + MI_W4;
    float* sBg = sMi + MI_BG;
    float* sFx = sMi + MI_FX;
    float* sFy = sMi + MI_FY;
    float* sVa = sMi + MI_VA;
    int*   sX0 = (int*)(sMi + MI_X0);
    int*   sY0 = (int*)(sMi + MI_Y0);
    float* sPx = sMi + MI_PX;
    float* sPy = sMi + MI_PY;
    float* sPz = sMi + MI_PZ;
    float* sPart = sMi + MI_PART;

    const int tid  = threadIdx.x;
    const int wid  = tid >> 5;
    const int lane = tid & 31;

    const int mslot = wid >> 1;
    const int nslot = wid & 1;
    const int g  = lane >> 2;
    const int t  = lane & 3;

    const uint32_t sAu  = smem_u32(sA);
    const uint32_t sW1u = smem_u32(sW1);

    const int arow = mslot * 32 + (lane & 15);
    const int acol = (lane >> 4) << 2;
    const uint32_t aBase0 = sAu + (uint32_t)(((arow)      * A_STRIDE + acol) << 2);
    const uint32_t aBase1 = sAu + (uint32_t)(((arow + 16) * A_STRIDE + acol) << 2);
    const int nrow = nslot * 32 + ((lane & 16) >> 1) + (lane & 7);
    const int ncol = (lane & 8) ? 4 : 0;
    const uint32_t b1Base0 = sW1u + (uint32_t)((nrow * W1_STRIDE + ncol) << 2);
    const uint32_t b1Base1 = b1Base0 + (uint32_t)(16 * W1_STRIDE * 4);

    // ---- one-time init ----
    {
        const float4* s = (const float4*)g_W1T;
        float4* d = (float4*)sW1;
        for (int i = tid; i < 64 * W1_STRIDE / 4; i += NTHREADS) d[i] = s[i];
    }
    if (tid < 64) {
        sB1[tid] = b1[tid]; sB2[tid] = b2[tid]; sB3[tid] = b3[tid];
        sW4[tid] = W4[tid];
    }
    if (tid < 96) ((float2*)sBg)[tid] = ((const float2*)Bg)[tid];
    const float b4v = b4[0];

    // stage W2/W3 into sA and hoist B-fragments to registers
    for (int i = tid; i < 64 * 64; i += NTHREADS) {
        int n = i >> 6, k = i & 63;
        sA[n * WST + k]            = g_W2Tc[i];
        sA[64 * WST + n * WST + k] = g_W3Tc[i];
    }
    __syncthreads();
    uint32_t B2f[64], B3f[64];
    {
        const int wrow = nslot * 32 + ((lane & 16) >> 1) + (lane & 7);
        const uint32_t wcol = (lane & 8) ? 4u : 0u;
        const uint32_t wBase0 = sAu + (uint32_t)(((wrow * WST + wcol)) << 2);
        const uint32_t wBase1 = wBase0 + (uint32_t)(16 * WST * 4);
        const uint32_t w3off  = (uint32_t)(64 * WST * 4);
#pragma unroll
        for (int kk = 0; kk < 8; ++kk) {
            ldsm4(B2f + kk * 8,     wBase0 + kk * 32);
            ldsm4(B2f + kk * 8 + 4, wBase1 + kk * 32);
            ldsm4(B3f + kk * 8,     wBase0 + w3off + kk * 32);
            ldsm4(B3f + kk * 8 + 4, wBase1 + w3off + kk * 32);
        }
    }
    __syncthreads();

    for (int tile = blockIdx.x; tile < NTILES; tile += GRID_CTAS) {
        const int p0 = tile * TILE_PTS;
        const int b  = p0 >> 16;

        // ---- projection (threads 0..127, one point each) ----
        if (tid < 128) {
            const float* pt = points + (size_t)(p0 + tid) * 3;
            const float px = pt[0], py = pt[1], pz = pt[2];
            const float* R = rtm + b * 12;
            const float* K = kmat + b * 9;
            const float cx = fmaf(R[0], px, fmaf(R[1], py, fmaf(R[2],  pz, R[3])));
            const float cy = fmaf(R[4], px, fmaf(R[5], py, fmaf(R[6],  pz, R[7])));
            const float cz = fmaf(R[8], px, fmaf(R[9], py, fmaf(R[10], pz, R[11])));
            const float ix = fmaf(K[0], cx, fmaf(K[1], cy, K[2] * cz));
            const float iy = fmaf(K[3], cx, fmaf(K[4], cy, K[5] * cz));
            const float iz = fmaf(K[6], cx, fmaf(K[7], cy, K[8] * cz));
            const bool  pos = (iz > 0.0f);
            const float zz = iz + 1e-8f;
            const float u = __fdividef(ix, zz), v = __fdividef(iy, zz);
            const float xf = floorf(u), yf = floorf(v);
            float fx = u - xf, fy = v - yf;
            int x0 = (int)xf, y0 = (int)yf;
            if (!pos) { x0 = -100000; y0 = -100000; fx = 0.0f; fy = 0.0f; }
            sFx[tid] = fx; sFy[tid] = fy; sVa[tid] = pos ? 1.0f : 0.0f;
            sX0[tid] = x0; sY0[tid] = y0;
            sPx[tid] = px; sPy[tid] = py; sPz[tid] = pz;
        }
        __syncthreads();

        // ---- warp-cooperative bilinear gather: 8 warps x 16 points ----
        {
            const int q0 = wid << 4;
            const float* baseb = g_tf + (size_t)b * 3136 * CHN + lane * 4;
#pragma unroll 2
            for (int i = 0; i < 16; ++i) {
                const int q = q0 + i;
                const float gfx = sFx[q], gfy = sFy[q], gv = sVa[q];
                const int gx = sX0[q], gy = sY0[q];
                const float ax = 1.0f - gfx, ay = 1.0f - gfy;
                const float w00 = ax * ay * gv;
                const float w10 = gfx * ay * gv;
                const float w01 = ax * gfy * gv;
                const float w11 = gfx * gfy * gv;
                const bool x0in = (gx >= 0) && (gx < WW);
                const bool x1in = (gx >= -1) && (gx < WW - 1);
                const bool y0in = (gy >= 0) && (gy < HH);
                const bool y1in = (gy >= -1) && (gy < HH - 1);
                const int rowoff = (gy * WW + gx) * CHN;
                float4 acc = make_float4(0.f, 0.f, 0.f, 0.f);
                if (x0in && y0in) {
                    float4 v4 = *(const float4*)(baseb + rowoff);
                    acc.x = fmaf(w00, v4.x, acc.x); acc.y = fmaf(w00, v4.y, acc.y);
                    acc.z = fmaf(w00, v4.z, acc.z); acc.w = fmaf(w00, v4.w, acc.w);
                }
                if (x1in && y0in) {
                    float4 v4 = *(const float4*)(baseb + rowoff + CHN);
                    acc.x = fmaf(w10, v4.x, acc.x); acc.y = fmaf(w10, v4.y, acc.y);
                    acc.z = fmaf(w10, v4.z, acc.z); acc.w = fmaf(w10, v4.w, acc.w);
                }
                if (x0in && y1in) {
                    float4 v4 = *(const float4*)(baseb + rowoff + WW * CHN);
                    acc.x = fmaf(w01, v4.x, acc.x); acc.y = fmaf(w01, v4.y, acc.y);
                    acc.z = fmaf(w01, v4.z, acc.z); acc.w = fmaf(w01, v4.w, acc.w);
                }
                if (x1in && y1in) {
                    float4 v4 = *(const float4*)(baseb + rowoff + (WW + 1) * CHN);
                    acc.x = fmaf(w11, v4.x, acc.x); acc.y = fmaf(w11, v4.y, acc.y);
                    acc.z = fmaf(w11, v4.z, acc.z); acc.w = fmaf(w11, v4.w, acc.w);
                }
                acc.x = to_tf32(acc.x); acc.y = to_tf32(acc.y);
                acc.z = to_tf32(acc.z); acc.w = to_tf32(acc.w);
                *(float4*)(sA + q * A_STRIDE + lane * 4) = acc;
            }
        }

        // ---- Fourier via FMA-pipe polynomial sincos (no MUFU) ----
        {
            const int q0 = wid << 4;
            const float bx0 = sBg[lane * 3],        by0 = sBg[lane * 3 + 1],        bz0 = sBg[lane * 3 + 2];
            const float bx1 = sBg[(lane + 32) * 3], by1 = sBg[(lane + 32) * 3 + 1], bz1 = sBg[(lane + 32) * 3 + 2];
            const float INV2PI = 0.15915494309189535f;  // turns per radian
#pragma unroll 2
            for (int i = 0; i < 16; ++i) {
                const int q = q0 + i;
                const float qx = sPx[q], qy = sPy[q], qz = sPz[q];
                // phase in turns: x_proj = 2*pi*(p . B) -> ph = p . B
                const float ph0 = fmaf(qx, bx0, fmaf(qy, by0, qz * bz0));
                const float ph1 = fmaf(qx, bx1, fmaf(qy, by1, qz * bz1));
                float s0, c0, s1, c1;
                sincos_2pi_fast(ph0, s0, c0);
                sincos_2pi_fast(ph1, s1, c1);
                float* row = sA + q * A_STRIDE;
                row[128 + lane]      = to_tf32(s0);
                row[128 + lane + 32] = to_tf32(s1);
                row[192 + lane]      = to_tf32(c0);
                row[192 + lane + 32] = to_tf32(c1);
                (void)INV2PI;
            }
        }
        __syncthreads();   // A fully built

        // ================= Layer 1: [128x256] @ W1 -> [128x64] =================
        float acc[2][4][4];
#pragma unroll
        for (int mt = 0; mt < 2; ++mt)
#pragma unroll
            for (int nt = 0; nt < 4; ++nt)
#pragma unroll
                for (int j = 0; j < 4; ++j) acc[mt][nt][j] = 0.0f;
#pragma unroll 4
        for (int kk = 0; kk < 32; ++kk) {
            uint32_t a0[4], a1[4], B[8];
            ldsm4(a0, aBase0 + kk * 32);
            ldsm4(a1, aBase1 + kk * 32);
            ldsm4(B,     b1Base0 + kk * 32);
            ldsm4(B + 4, b1Base1 + kk * 32);
            mma16n8k8(acc[0][0], a0, B[0], B[1]);
            mma16n8k8(acc[0][1], a0, B[2], B[3]);
            mma16n8k8(acc[0][2], a0, B[4], B[5]);
            mma16n8k8(acc[0][3], a0, B[6], B[7]);
            mma16n8k8(acc[1][0], a1, B[0], B[1]);
            mma16n8k8(acc[1][1], a1, B[2], B[3]);
            mma16n8k8(acc[1][2], a1, B[4], B[5]);
            mma16n8k8(acc[1][3], a1, B[6], B[7]);
        }
        __syncthreads();   // all L1 A-reads done

        // relu(acc + b1) -> A cols [0,64)
#pragma unroll
        for (int mt = 0; mt < 2; ++mt) {
            const int r0 = mslot * 32 + mt * 16 + g;
#pragma unroll
            for (int nt = 0; nt < 4; ++nt) {
                const int col = nslot * 32 + nt * 8 + t * 2;
                float2 v0, v1;
                v0.x = to_tf32(fmaxf(acc[mt][nt][0] + sB1[col], 0.f));
                v0.y = to_tf32(fmaxf(acc[mt][nt][1] + sB1[col + 1], 0.f));
                v1.x = to_tf32(fmaxf(acc[mt][nt][2] + sB1[col], 0.f));
                v1.y = to_tf32(fmaxf(acc[mt][nt][3] + sB1[col + 1], 0.f));
                *(float2*)(sA + r0 * A_STRIDE + col) = v0;
                *(float2*)(sA + (r0 + 8) * A_STRIDE + col) = v1;
            }
        }
        __syncthreads();   // h1 ready

        // ================= Layer 2: h1 @ W2 (B in registers) =================
#pragma unroll
        for (int mt = 0; mt < 2; ++mt)
#pragma unroll
            for (int nt = 0; nt < 4; ++nt)
#pragma unroll
                for (int j = 0; j < 4; ++j) acc[mt][nt][j] = 0.0f;
#pragma unroll
        for (int kk = 0; kk < 8; ++kk) {
            uint32_t a0[4], a1[4];
            ldsm4(a0, aBase0 + kk * 32);
            ldsm4(a1, aBase1 + kk * 32);
#pragma unroll
            for (int nt = 0; nt < 4; ++nt) {
                mma16n8k8(acc[0][nt], a0, B2f[kk * 8 + nt * 2], B2f[kk * 8 + nt * 2 + 1]);
                mma16n8k8(acc[1][nt], a1, B2f[kk * 8 + nt * 2], B2f[kk * 8 + nt * 2 + 1]);
            }
        }
        // relu(acc + b2) -> A cols [64,128)
#pragma unroll
        for (int mt = 0; mt < 2; ++mt) {
            const int r0 = mslot * 32 + mt * 16 + g;
#pragma unroll
            for (int nt = 0; nt < 4; ++nt) {
                const int col = nslot * 32 + nt * 8 + t * 2;
                float2 v0, v1;
                v0.x = to_tf32(fmaxf(acc[mt][nt][0] + sB2[col], 0.f));
                v0.y = to_tf32(fmaxf(acc[mt][nt][1] + sB2[col + 1], 0.f));
                v1.x = to_tf32(fmaxf(acc[mt][nt][2] + sB2[col], 0.f));
                v1.y = to_tf32(fmaxf(acc[mt][nt][3] + sB2[col + 1], 0.f));
                *(float2*)(sA + r0 * A_STRIDE + 64 + col) = v0;
                *(float2*)(sA + (r0 + 8) * A_STRIDE + 64 + col) = v1;
            }
        }
        __syncthreads();   // h2 ready

        // ================= Layer 3: h2 @ W3 (B in registers) =================
#pragma unroll
        for (int mt = 0; mt < 2; ++mt)
#pragma unroll
            for (int nt = 0; nt < 4; ++nt)
#pragma unroll
                for (int j = 0; j < 4; ++j) acc[mt][nt][j] = 0.0f;
#pragma unroll
        for (int kk = 0; kk < 8; ++kk) {
            uint32_t a0[4], a1[4];
            ldsm4(a0, aBase0 + 256 + kk * 32);   // cols [64,128)
            ldsm4(a1, aBase1 + 256 + kk * 32);
#pragma unroll
            for (int nt = 0; nt < 4; ++nt) {
                mma16n8k8(acc[0][nt], a0, B3f[kk * 8 + nt * 2], B3f[kk * 8 + nt * 2 + 1]);
                mma16n8k8(acc[1][nt], a1, B3f[kk * 8 + nt * 2], B3f[kk * 8 + nt * 2 + 1]);
            }
        }

        // ---- layer 4 epilogue ----
        {
            float pr[2][2];
            pr[0][0] = pr[0][1] = pr[1][0] = pr[1][1] = 0.0f;
#pragma unroll
            for (int mt = 0; mt < 2; ++mt)
#pragma unroll
                for (int nt = 0; nt < 4; ++nt) {
                    const int col = nslot * 32 + nt * 8 + t * 2;
                    pr[mt][0] = fmaf(fmaxf(acc[mt][nt][0] + sB3[col], 0.f),     sW4[col],     pr[mt][0]);
                    pr[mt][0] = fmaf(fmaxf(acc[mt][nt][1] + sB3[col + 1], 0.f), sW4[col + 1], pr[mt][0]);
                    pr[mt][1] = fmaf(fmaxf(acc[mt][nt][2] + sB3[col], 0.f),     sW4[col],     pr[mt][1]);
                    pr[mt][1] = fmaf(fmaxf(acc[mt][nt][3] + sB3[col + 1], 0.f), sW4[col + 1], pr[mt][1]);
                }
#pragma unroll
            for (int mt = 0; mt < 2; ++mt) {
                pr[mt][0] += __shfl_xor_sync(0xffffffffu, pr[mt][0], 1);
                pr[mt][0] += __shfl_xor_sync(0xffffffffu, pr[mt][0], 2);
                pr[mt][1] += __shfl_xor_sync(0xffffffffu, pr[mt][1], 1);
                pr[mt][1] += __shfl_xor_sync(0xffffffffu, pr[mt][1], 2);
                if (t == 0) {
                    const int r0 = mslot * 32 + mt * 16 + g;
                    sPart[nslot * 128 + r0] = pr[mt][0];
                    sPart[nslot * 128 + r0 + 8] = pr[mt][1];
                }
            }
        }
        __syncthreads();
        if (tid < 128) out[p0 + tid] = sPart[tid] + sPart[128 + tid] + b4v;
    }
}

// ---------------------------------------------------------------------------
// Launch
// ---------------------------------------------------------------------------
extern "C" void kernel_launch(void* const* d_in, const int* in_sizes, int n_in,
                              void* d_out, int out_size) {
    const float* features = (const float*)d_in[0];
    const float* points   = (const float*)d_in[1];
    const float* kmat     = (const float*)d_in[2];
    const float* rtm      = (const float*)d_in[3];
    const float* Bg       = (const float*)d_in[4];
    const float* W1 = (const float*)d_in[5];
    const float* b1 = (const float*)d_in[6];
    const float* W2 = (const float*)d_in[7];
    const float* b2 = (const float*)d_in[8];
    const float* W3 = (const float*)d_in[9];
    const float* b3 = (const float*)d_in[10];
    const float* W4 = (const float*)d_in[11];
    const float* b4 = (const float*)d_in[12];

    dim3 tb(32, 32);
    dim3 tg(3136 / 32, CHN / 32, BATCH);
    transpose_kernel<<<tg, tb>>>(features, W1, W2, W3);

    cudaFuncSetAttribute(decoder_kernel,
                         cudaFuncAttributeMaxDynamicSharedMemorySize, SMEM_TOTAL);
    decoder_kernel<<<GRID_CTAS, NTHREADS, SMEM_TOTAL>>>(
        points, kmat, rtm, Bg, b1, b2, b3, W4, b4, (float*)d_out);
}

// round 8
// speedup vs baseline: 1.1988x; 1.1988x over previous
#include <cuda_runtime.h>
#include <math.h>
#include <stdint.h>

#define BATCH 8
#define CHN 128
#define HH 56
#define WW 56
#define TILE_PTS 128
#define NTHREADS 256
#define NTILES 4096
#define GRID_CTAS 148

#define A_STRIDE 260     // 65 x 16B rows: %8==1 -> conflict-free LDSM
#define W1_STRIDE 260
#define WST 68           // staging stride for W2/W3 (%8==4, conflict-free)

// float-index offsets in dynamic smem
#define FOFF_A     0                          // 128 x 260
#define FOFF_W1    (128 * A_STRIDE)           // 64 x 260
#define FOFF_MISC  (FOFF_W1 + 64 * W1_STRIDE)
#define MI_B1   0
#define MI_B2   64
#define MI_B3   128
#define MI_W4   192
#define MI_BG   256      // 192 floats
#define MI_FX   448
#define MI_FY   576
#define MI_VA   704
#define MI_X0   832
#define MI_Y0   960
#define MI_PX   1088
#define MI_PY   1216
#define MI_PZ   1344
#define MI_PART 1472     // 256 floats
#define SMEM_TOTAL ((FOFF_MISC + 1792) * 4)   // 206,848 bytes

// group barrier: named barrier per 128-thread group
#define GBAR(grp) asm volatile("bar.sync %0, 128;" :: "r"((grp) + 1) : "memory")

// ---------------- globals ----------------
__device__ float g_tf[BATCH * HH * WW * CHN];   // (B,H,W,C) features
__device__ float g_W1T[64 * W1_STRIDE];         // n-major padded tf32 image
__device__ float g_W2Tc[64 * 64];               // compact n-major tf32
__device__ float g_W3Tc[64 * 64];

__device__ __forceinline__ float to_tf32(float x) {
    uint32_t r;
    asm("cvt.rna.tf32.f32 %0, %1;" : "=r"(r) : "f"(x));
    return __uint_as_float(r);
}
__device__ __forceinline__ uint32_t smem_u32(const void* p) {
    uint32_t a;
    asm("{ .reg .u64 t; cvta.to.shared.u64 t, %1; cvt.u32.u64 %0, t; }" : "=r"(a) : "l"(p));
    return a;
}
__device__ __forceinline__ void ldsm4(uint32_t* r, uint32_t addr) {
    asm volatile("ldmatrix.sync.aligned.m8n8.x4.shared.b16 {%0,%1,%2,%3}, [%4];"
                 : "=r"(r[0]), "=r"(r[1]), "=r"(r[2]), "=r"(r[3]) : "r"(addr));
}
__device__ __forceinline__ void mma16n8k8(float* d, const uint32_t* a, uint32_t b0, uint32_t b1) {
    asm volatile(
        "mma.sync.aligned.m16n8k8.row.col.f32.tf32.tf32.f32 "
        "{%0,%1,%2,%3}, {%4,%5,%6,%7}, {%8,%9}, {%0,%1,%2,%3};"
        : "+f"(d[0]), "+f"(d[1]), "+f"(d[2]), "+f"(d[3])
        : "r"(a[0]), "r"(a[1]), "r"(a[2]), "r"(a[3]), "r"(b0), "r"(b1));
}

// ---------------------------------------------------------------------------
// Kernel 1: transpose features + prep weight images (merged)
// ---------------------------------------------------------------------------
__global__ void transpose_kernel(const float* __restrict__ f,
                                 const float* __restrict__ W1,
                                 const float* __restrict__ W2,
                                 const float* __restrict__ W3) {
    __shared__ float tile[32][33];
    const int b  = blockIdx.z;
    const int c0 = blockIdx.y << 5;
    const int s0 = blockIdx.x << 5;
    const int tx = threadIdx.x, ty = threadIdx.y;
    tile[ty][tx] = f[(size_t)(b * CHN + c0 + ty) * 3136 + (s0 + tx)];
    __syncthreads();
    g_tf[(size_t)(b * 3136 + s0 + ty) * CHN + (c0 + tx)] = tile[tx][ty];

    if (blockIdx.x == 0 && blockIdx.y == 0) {
        const int t = ty * 32 + tx;
        const int base = b * 1024 + t;
        for (int i = base; i < 64 * 256; i += 8192) {
            int n = i & 63, k = i >> 6;
            g_W1T[n * W1_STRIDE + k] = to_tf32(W1[k * 64 + n]);
        }
        for (int i = base; i < 64 * 64; i += 8192) {
            int n = i & 63, k = i >> 6;
            g_W2Tc[n * 64 + k] = to_tf32(W2[k * 64 + n]);
            g_W3Tc[n * 64 + k] = to_tf32(W3[k * 64 + n]);
        }
    }
}

// ---------------------------------------------------------------------------
// Kernel 2: persistent fused decoder — two independent 4-warp groups
// ---------------------------------------------------------------------------
__global__ __launch_bounds__(NTHREADS, 1)
void decoder_kernel(const float* __restrict__ points,
                    const float* __restrict__ kmat,
                    const float* __restrict__ rtm,
                    const float* __restrict__ Bg,
                    const float* __restrict__ b1,
                    const float* __restrict__ b2,
                    const float* __restrict__ b3,
                    const float* __restrict__ W4,
                    const float* __restrict__ b4,
                    float* __restrict__ out) {
    extern __shared__ float sm[];
    float* sA  = sm + FOFF_A;
    float* sW1 = sm + FOFF_W1;
    float* sMi = sm + FOFF_MISC;
    float* sB1 = sMi + MI_B1;
    float* sB2 = sMi + MI_B2;
    float* sB3 = sMi + MI_B3;
    float* sW4 = sMi + MI_W4;
    float* sBg = sMi + MI_BG;
    float* sFx = sMi + MI_FX;
    float* sFy = sMi + MI_FY;
    float* sVa = sMi + MI_VA;
    int*   sX0 = (int*)(sMi + MI_X0);
    int*   sY0 = (int*)(sMi + MI_Y0);
    float* sPx = sMi + MI_PX;
    float* sPy = sMi + MI_PY;
    float* sPz = sMi + MI_PZ;
    float* sPart = sMi + MI_PART;

    const int tid  = threadIdx.x;
    const int wid  = tid >> 5;
    const int lane = tid & 31;

    const int grp  = wid >> 2;        // group 0 / 1: owns points grp*64..+64
    const int gw   = wid & 3;         // warp within group
    const int gtid = tid & 127;       // thread within group
    const int mslot = gw >> 1;        // 0..1: 32-row slice within group half
    const int nslot = gw & 1;         // 0..1: 32-col slice
    const int gg = lane >> 2;
    const int t  = lane & 3;

    const uint32_t sAu  = smem_u32(sA);
    const uint32_t sW1u = smem_u32(sW1);

    // A-frag ldsm addresses (two m16 tiles within this group's 64 rows)
    const int arow = grp * 64 + mslot * 32 + (lane & 15);
    const int acol = (lane >> 4) << 2;
    const uint32_t aBase0 = sAu + (uint32_t)(((arow)      * A_STRIDE + acol) << 2);
    const uint32_t aBase1 = sAu + (uint32_t)(((arow + 16) * A_STRIDE + acol) << 2);
    // W1 B-frag addresses
    const int nrow = nslot * 32 + ((lane & 16) >> 1) + (lane & 7);
    const int ncol = (lane & 8) ? 4 : 0;
    const uint32_t b1Base0 = sW1u + (uint32_t)((nrow * W1_STRIDE + ncol) << 2);
    const uint32_t b1Base1 = b1Base0 + (uint32_t)(16 * W1_STRIDE * 4);

    // ---- one-time init (whole CTA) ----
    {
        const float4* s = (const float4*)g_W1T;
        float4* d = (float4*)sW1;
        for (int i = tid; i < 64 * W1_STRIDE / 4; i += NTHREADS) d[i] = s[i];
    }
    if (tid < 64) {
        sB1[tid] = b1[tid]; sB2[tid] = b2[tid]; sB3[tid] = b3[tid];
        sW4[tid] = W4[tid];
    }
    if (tid < 96) ((float2*)sBg)[tid] = ((const float2*)Bg)[tid];
    const float b4v = b4[0];

    // stage W2/W3 into sA and hoist B-fragments to registers
    for (int i = tid; i < 64 * 64; i += NTHREADS) {
        int n = i >> 6, k = i & 63;
        sA[n * WST + k]            = g_W2Tc[i];
        sA[64 * WST + n * WST + k] = g_W3Tc[i];
    }
    __syncthreads();
    uint32_t B2f[64], B3f[64];
    {
        const int wrow = nslot * 32 + ((lane & 16) >> 1) + (lane & 7);
        const uint32_t wcol = (lane & 8) ? 4u : 0u;
        const uint32_t wBase0 = sAu + (uint32_t)(((wrow * WST + wcol)) << 2);
        const uint32_t wBase1 = wBase0 + (uint32_t)(16 * WST * 4);
        const uint32_t w3off  = (uint32_t)(64 * WST * 4);
#pragma unroll
        for (int kk = 0; kk < 8; ++kk) {
            ldsm4(B2f + kk * 8,     wBase0 + kk * 32);
            ldsm4(B2f + kk * 8 + 4, wBase1 + kk * 32);
            ldsm4(B3f + kk * 8,     wBase0 + w3off + kk * 32);
            ldsm4(B3f + kk * 8 + 4, wBase1 + w3off + kk * 32);
        }
    }
    __syncthreads();

    for (int tile = blockIdx.x; tile < NTILES; tile += GRID_CTAS) {
        const int p0 = tile * TILE_PTS;
        const int b  = p0 >> 16;

        // ---- projection: first 64 threads of group handle its 64 points ----
        if (gtid < 64) {
            const int pq = grp * 64 + gtid;          // point id within tile
            const float* pt = points + (size_t)(p0 + pq) * 3;
            const float px = pt[0], py = pt[1], pz = pt[2];
            const float* R = rtm + b * 12;
            const float* K = kmat + b * 9;
            const float cx = fmaf(R[0], px, fmaf(R[1], py, fmaf(R[2],  pz, R[3])));
            const float cy = fmaf(R[4], px, fmaf(R[5], py, fmaf(R[6],  pz, R[7])));
            const float cz = fmaf(R[8], px, fmaf(R[9], py, fmaf(R[10], pz, R[11])));
            const float ix = fmaf(K[0], cx, fmaf(K[1], cy, K[2] * cz));
            const float iy = fmaf(K[3], cx, fmaf(K[4], cy, K[5] * cz));
            const float iz = fmaf(K[6], cx, fmaf(K[7], cy, K[8] * cz));
            const bool  pos = (iz > 0.0f);
            const float zz = iz + 1e-8f;
            const float u = __fdividef(ix, zz), v = __fdividef(iy, zz);
            const float xf = floorf(u), yf = floorf(v);
            float fx = u - xf, fy = v - yf;
            int x0 = (int)xf, y0 = (int)yf;
            if (!pos) { x0 = -100000; y0 = -100000; fx = 0.0f; fy = 0.0f; }
            sFx[pq] = fx; sFy[pq] = fy; sVa[pq] = pos ? 1.0f : 0.0f;
            sX0[pq] = x0; sY0[pq] = y0;
            sPx[pq] = px; sPy[pq] = py; sPz[pq] = pz;
        }
        GBAR(grp);

        // ---- warp-cooperative bilinear gather: 4 warps x 16 points ----
        {
            const int q0 = grp * 64 + gw * 16;
            const float* baseb = g_tf + (size_t)b * 3136 * CHN + lane * 4;
#pragma unroll 4
            for (int i = 0; i < 16; ++i) {
                const int q = q0 + i;
                const float gfx = sFx[q], gfy = sFy[q], gv = sVa[q];
                const int gx = sX0[q], gy = sY0[q];
                const float ax = 1.0f - gfx, ay = 1.0f - gfy;
                const float w00 = ax * ay * gv;
                const float w10 = gfx * ay * gv;
                const float w01 = ax * gfy * gv;
                const float w11 = gfx * gfy * gv;
                const bool x0in = (gx >= 0) && (gx < WW);
                const bool x1in = (gx >= -1) && (gx < WW - 1);
                const bool y0in = (gy >= 0) && (gy < HH);
                const bool y1in = (gy >= -1) && (gy < HH - 1);
                const int rowoff = (gy * WW + gx) * CHN;
                float4 acc = make_float4(0.f, 0.f, 0.f, 0.f);
                if (x0in && y0in) {
                    float4 v4 = *(const float4*)(baseb + rowoff);
                    acc.x = fmaf(w00, v4.x, acc.x); acc.y = fmaf(w00, v4.y, acc.y);
                    acc.z = fmaf(w00, v4.z, acc.z); acc.w = fmaf(w00, v4.w, acc.w);
                }
                if (x1in && y0in) {
                    float4 v4 = *(const float4*)(baseb + rowoff + CHN);
                    acc.x = fmaf(w10, v4.x, acc.x); acc.y = fmaf(w10, v4.y, acc.y);
                    acc.z = fmaf(w10, v4.z, acc.z); acc.w = fmaf(w10, v4.w, acc.w);
                }
                if (x0in && y1in) {
                    float4 v4 = *(const float4*)(baseb + rowoff + WW * CHN);
                    acc.x = fmaf(w01, v4.x, acc.x); acc.y = fmaf(w01, v4.y, acc.y);
                    acc.z = fmaf(w01, v4.z, acc.z); acc.w = fmaf(w01, v4.w, acc.w);
                }
                if (x1in && y1in) {
                    float4 v4 = *(const float4*)(baseb + rowoff + (WW + 1) * CHN);
                    acc.x = fmaf(w11, v4.x, acc.x); acc.y = fmaf(w11, v4.y, acc.y);
                    acc.z = fmaf(w11, v4.z, acc.z); acc.w = fmaf(w11, v4.w, acc.w);
                }
                acc.x = to_tf32(acc.x); acc.y = to_tf32(acc.y);
                acc.z = to_tf32(acc.z); acc.w = to_tf32(acc.w);
                *(float4*)(sA + q * A_STRIDE + lane * 4) = acc;
            }
        }

        // ---- Fourier (MUFU): lanes write consecutive columns ----
        {
            const float TWOPI = 6.283185307179586f;
            const int q0 = grp * 64 + gw * 16;
            const float bx0 = sBg[lane * 3],        by0 = sBg[lane * 3 + 1],        bz0 = sBg[lane * 3 + 2];
            const float bx1 = sBg[(lane + 32) * 3], by1 = sBg[(lane + 32) * 3 + 1], bz1 = sBg[(lane + 32) * 3 + 2];
#pragma unroll 2
            for (int i = 0; i < 16; ++i) {
                const int q = q0 + i;
                const float qx = sPx[q], qy = sPy[q], qz = sPz[q];
                const float xp0 = TWOPI * fmaf(qx, bx0, fmaf(qy, by0, qz * bz0));
                const float xp1 = TWOPI * fmaf(qx, bx1, fmaf(qy, by1, qz * bz1));
                float* row = sA + q * A_STRIDE;
                row[128 + lane]      = to_tf32(__sinf(xp0));
                row[128 + lane + 32] = to_tf32(__sinf(xp1));
                row[192 + lane]      = to_tf32(__cosf(xp0));
                row[192 + lane + 32] = to_tf32(__cosf(xp1));
            }
        }
        GBAR(grp);   // group's A half fully built

        // ================= Layer 1: [64x256] @ W1 -> [64x64] =================
        float acc[2][4][4];
#pragma unroll
        for (int mt = 0; mt < 2; ++mt)
#pragma unroll
            for (int nt = 0; nt < 4; ++nt)
#pragma unroll
                for (int j = 0; j < 4; ++j) acc[mt][nt][j] = 0.0f;
#pragma unroll 4
        for (int kk = 0; kk < 32; ++kk) {
            uint32_t a0[4], a1[4], B[8];
            ldsm4(a0, aBase0 + kk * 32);
            ldsm4(a1, aBase1 + kk * 32);
            ldsm4(B,     b1Base0 + kk * 32);
            ldsm4(B + 4, b1Base1 + kk * 32);
            mma16n8k8(acc[0][0], a0, B[0], B[1]);
            mma16n8k8(acc[0][1], a0, B[2], B[3]);
            mma16n8k8(acc[0][2], a0, B[4], B[5]);
            mma16n8k8(acc[0][3], a0, B[6], B[7]);
            mma16n8k8(acc[1][0], a1, B[0], B[1]);
            mma16n8k8(acc[1][1], a1, B[2], B[3]);
            mma16n8k8(acc[1][2], a1, B[4], B[5]);
            mma16n8k8(acc[1][3], a1, B[6], B[7]);
        }
        GBAR(grp);   // group's L1 A-reads done

        // relu(acc + b1) -> A cols [0,64) of group's rows
#pragma unroll
        for (int mt = 0; mt < 2; ++mt) {
            const int r0 = grp * 64 + mslot * 32 + mt * 16 + gg;
#pragma unroll
            for (int nt = 0; nt < 4; ++nt) {
                const int col = nslot * 32 + nt * 8 + t * 2;
                float2 v0, v1;
                v0.x = to_tf32(fmaxf(acc[mt][nt][0] + sB1[col], 0.f));
                v0.y = to_tf32(fmaxf(acc[mt][nt][1] + sB1[col + 1], 0.f));
                v1.x = to_tf32(fmaxf(acc[mt][nt][2] + sB1[col], 0.f));
                v1.y = to_tf32(fmaxf(acc[mt][nt][3] + sB1[col + 1], 0.f));
                *(float2*)(sA + r0 * A_STRIDE + col) = v0;
                *(float2*)(sA + (r0 + 8) * A_STRIDE + col) = v1;
            }
        }
        GBAR(grp);   // h1 ready

        // ================= Layer 2: h1 @ W2 (B in registers) =================
#pragma unroll
        for (int mt = 0; mt < 2; ++mt)
#pragma unroll
            for (int nt = 0; nt < 4; ++nt)
#pragma unroll
                for (int j = 0; j < 4; ++j) acc[mt][nt][j] = 0.0f;
#pragma unroll
        for (int kk = 0; kk < 8; ++kk) {
            uint32_t a0[4], a1[4];
            ldsm4(a0, aBase0 + kk * 32);
            ldsm4(a1, aBase1 + kk * 32);
#pragma unroll
            for (int nt = 0; nt < 4; ++nt) {
                mma16n8k8(acc[0][nt], a0, B2f[kk * 8 + nt * 2], B2f[kk * 8 + nt * 2 + 1]);
                mma16n8k8(acc[1][nt], a1, B2f[kk * 8 + nt * 2], B2f[kk * 8 + nt * 2 + 1]);
            }
        }
        // relu(acc + b2) -> A cols [64,128) (disjoint from this layer's reads)
#pragma unroll
        for (int mt = 0; mt < 2; ++mt) {
            const int r0 = grp * 64 + mslot * 32 + mt * 16 + gg;
#pragma unroll
            for (int nt = 0; nt < 4; ++nt) {
                const int col = nslot * 32 + nt * 8 + t * 2;
                float2 v0, v1;
                v0.x = to_tf32(fmaxf(acc[mt][nt][0] + sB2[col], 0.f));
                v0.y = to_tf32(fmaxf(acc[mt][nt][1] + sB2[col + 1], 0.f));
                v1.x = to_tf32(fmaxf(acc[mt][nt][2] + sB2[col], 0.f));
                v1.y = to_tf32(fmaxf(acc[mt][nt][3] + sB2[col + 1], 0.f));
                *(float2*)(sA + r0 * A_STRIDE + 64 + col) = v0;
                *(float2*)(sA + (r0 + 8) * A_STRIDE + 64 + col) = v1;
            }
        }
        GBAR(grp);   // h2 ready

        // ================= Layer 3: h2 @ W3 (B in registers) =================
#pragma unroll
        for (int mt = 0; mt < 2; ++mt)
#pragma unroll
            for (int nt = 0; nt < 4; ++nt)
#pragma unroll
                for (int j = 0; j < 4; ++j) acc[mt][nt][j] = 0.0f;
#pragma unroll
        for (int kk = 0; kk < 8; ++kk) {
            uint32_t a0[4], a1[4];
            ldsm4(a0, aBase0 + 256 + kk * 32);   // cols [64,128)
            ldsm4(a1, aBase1 + 256 + kk * 32);
#pragma unroll
            for (int nt = 0; nt < 4; ++nt) {
                mma16n8k8(acc[0][nt], a0, B3f[kk * 8 + nt * 2], B3f[kk * 8 + nt * 2 + 1]);
                mma16n8k8(acc[1][nt], a1, B3f[kk * 8 + nt * 2], B3f[kk * 8 + nt * 2 + 1]);
            }
        }

        // ---- layer 4 epilogue ----
        {
            float pr[2][2];
            pr[0][0] = pr[0][1] = pr[1][0] = pr[1][1] = 0.0f;
#pragma unroll
            for (int mt = 0; mt < 2; ++mt)
#pragma unroll
                for (int nt = 0; nt < 4; ++nt) {
                    const int col = nslot * 32 + nt * 8 + t * 2;
                    pr[mt][0] = fmaf(fmaxf(acc[mt][nt][0] + sB3[col], 0.f),     sW4[col],     pr[mt][0]);
                    pr[mt][0] = fmaf(fmaxf(acc[mt][nt][1] + sB3[col + 1], 0.f), sW4[col + 1], pr[mt][0]);
                    pr[mt][1] = fmaf(fmaxf(acc[mt][nt][2] + sB3[col], 0.f),     sW4[col],     pr[mt][1]);
                    pr[mt][1] = fmaf(fmaxf(acc[mt][nt][3] + sB3[col + 1], 0.f), sW4[col + 1], pr[mt][1]);
                }
#pragma unroll
            for (int mt = 0; mt < 2; ++mt) {
                pr[mt][0] += __shfl_xor_sync(0xffffffffu, pr[mt][0], 1);
                pr[mt][0] += __shfl_xor_sync(0xffffffffu, pr[mt][0], 2);
                pr[mt][1] += __shfl_xor_sync(0xffffffffu, pr[mt][1], 1);
                pr[mt][1] += __shfl_xor_sync(0xffffffffu, pr[mt][1], 2);
                if (t == 0) {
                    const int lr = mslot * 32 + mt * 16 + gg;       // local row 0..63
                    sPart[grp * 128 + nslot * 64 + lr] = pr[mt][0];
                    sPart[grp * 128 + nslot * 64 + lr + 8] = pr[mt][1];
                }
            }
        }
        GBAR(grp);   // sPart half ready; group's L3 A-reads done
        if (gtid < 64)
            out[p0 + grp * 64 + gtid] =
                sPart[grp * 128 + gtid] + sPart[grp * 128 + 64 + gtid] + b4v;
    }
}

// ---------------------------------------------------------------------------
// Launch
// ---------------------------------------------------------------------------
extern "C" void kernel_launch(void* const* d_in, const int* in_sizes, int n_in,
                              void* d_out, int out_size) {
    const float* features = (const float*)d_in[0];
    const float* points   = (const float*)d_in[1];
    const float* kmat     = (const float*)d_in[2];
    const float* rtm      = (const float*)d_in[3];
    const float* Bg       = (const float*)d_in[4];
    const float* W1 = (const float*)d_in[5];
    const float* b1 = (const float*)d_in[6];
    const float* W2 = (const float*)d_in[7];
    const float* b2 = (const float*)d_in[8];
    const float* W3 = (const float*)d_in[9];
    const float* b3 = (const float*)d_in[10];
    const float* W4 = (const float*)d_in[11];
    const float* b4 = (const float*)d_in[12];

    dim3 tb(32, 32);
    dim3 tg(3136 / 32, CHN / 32, BATCH);
    transpose_kernel<<<tg, tb>>>(features, W1, W2, W3);

    cudaFuncSetAttribute(decoder_kernel,
                         cudaFuncAttributeMaxDynamicSharedMemorySize, SMEM_TOTAL);
    decoder_kernel<<<GRID_CTAS, NTHREADS, SMEM_TOTAL>>>(
        points, kmat, rtm, Bg, b1, b2, b3, W4, b4, (float*)d_out);
}

// round 10
// speedup vs baseline: 1.3666x; 1.1400x over previous
#include <cuda_runtime.h>
#include <math.h>
#include <stdint.h>

#define BATCH 8
#define CHN 128
#define HH 56
#define WW 56
#define TILE_PTS 128
#define NTHREADS 256
#define NTILES 4096
#define GRID_CTAS 148

#define A_STRIDE 260     // 65 x 16B rows: %8==1 -> conflict-free LDSM
#define W1_STRIDE 260
#define WST 68           // stride for W2/W3 stage (%8==4, conflict-free)

// float-index offsets in dynamic smem
#define FOFF_A     0                          // 128 x 260
#define FOFF_W1    (128 * A_STRIDE)           // 64 x 260
#define FOFF_MISC  (FOFF_W1 + 64 * W1_STRIDE)
#define MI_B1   0
#define MI_B2   64
#define MI_B3   128
#define MI_W4   192
#define MI_BG   256      // 192 floats
#define MI_PART 448      // 256 floats
#define MISC_FLOATS 768
#define FOFF_W3    (FOFF_MISC + MISC_FLOATS)  // 64 x 68 persistent W3 image
#define SMEM_TOTAL ((FOFF_W3 + 64 * WST) * 4) // 221,952 bytes

#define GBAR(grp) asm volatile("bar.sync %0, 128;" :: "r"((grp) + 1) : "memory")

// ---------------- globals ----------------
__device__ float g_tf[BATCH * HH * WW * CHN];   // (B,H,W,C) features
__device__ float g_W1T[64 * W1_STRIDE];         // n-major padded tf32 image
__device__ float g_W2Tc[64 * 64];               // compact n-major tf32
__device__ float g_W3Tc[64 * 64];

__device__ __forceinline__ float to_tf32(float x) {
    uint32_t r;
    asm("cvt.rna.tf32.f32 %0, %1;" : "=r"(r) : "f"(x));
    return __uint_as_float(r);
}
__device__ __forceinline__ uint32_t smem_u32(const void* p) {
    uint32_t a;
    asm("{ .reg .u64 t; cvta.to.shared.u64 t, %1; cvt.u32.u64 %0, t; }" : "=r"(a) : "l"(p));
    return a;
}
__device__ __forceinline__ void ldsm4(uint32_t* r, uint32_t addr) {
    asm volatile("ldmatrix.sync.aligned.m8n8.x4.shared.b16 {%0,%1,%2,%3}, [%4];"
                 : "=r"(r[0]), "=r"(r[1]), "=r"(r[2]), "=r"(r[3]) : "r"(addr));
}
__device__ __forceinline__ void mma16n8k8(float* d, const uint32_t* a, uint32_t b0, uint32_t b1) {
    asm volatile(
        "mma.sync.aligned.m16n8k8.row.col.f32.tf32.tf32.f32 "
        "{%0,%1,%2,%3}, {%4,%5,%6,%7}, {%8,%9}, {%0,%1,%2,%3};"
        : "+f"(d[0]), "+f"(d[1]), "+f"(d[2]), "+f"(d[3])
        : "r"(a[0]), "r"(a[1]), "r"(a[2]), "r"(a[3]), "r"(b0), "r"(b1));
}

// ---------------------------------------------------------------------------
// Kernel 1: transpose features + prep weight images (merged)
// ---------------------------------------------------------------------------
__global__ void transpose_kernel(const float* __restrict__ f,
                                 const float* __restrict__ W1,
                                 const float* __restrict__ W2,
                                 const float* __restrict__ W3) {
    __shared__ float tile[32][33];
    const int b  = blockIdx.z;
    const int c0 = blockIdx.y << 5;
    const int s0 = blockIdx.x << 5;
    const int tx = threadIdx.x, ty = threadIdx.y;
    tile[ty][tx] = f[(size_t)(b * CHN + c0 + ty) * 3136 + (s0 + tx)];
    __syncthreads();
    g_tf[(size_t)(b * 3136 + s0 + ty) * CHN + (c0 + tx)] = tile[tx][ty];

    if (blockIdx.x == 0 && blockIdx.y == 0) {
        const int t = ty * 32 + tx;
        const int base = b * 1024 + t;
        for (int i = base; i < 64 * 256; i += 8192) {
            int n = i & 63, k = i >> 6;
            g_W1T[n * W1_STRIDE + k] = to_tf32(W1[k * 64 + n]);
        }
        for (int i = base; i < 64 * 64; i += 8192) {
            int n = i & 63, k = i >> 6;
            g_W2Tc[n * 64 + k] = to_tf32(W2[k * 64 + n]);
            g_W3Tc[n * 64 + k] = to_tf32(W3[k * 64 + n]);
        }
    }
}

// ---------------------------------------------------------------------------
// Kernel 2: persistent fused decoder — 2 groups x 4 warps, pipelined MMA
// ---------------------------------------------------------------------------
__global__ __launch_bounds__(NTHREADS, 1)
void decoder_kernel(const float* __restrict__ points,
                    const float* __restrict__ kmat,
                    const float* __restrict__ rtm,
                    const float* __restrict__ Bg,
                    const float* __restrict__ b1,
                    const float* __restrict__ b2,
                    const float* __restrict__ b3,
                    const float* __restrict__ W4,
                    const float* __restrict__ b4,
                    float* __restrict__ out) {
    extern __shared__ float sm[];
    float* sA  = sm + FOFF_A;
    float* sW1 = sm + FOFF_W1;
    float* sW3 = sm + FOFF_W3;
    float* sMi = sm + FOFF_MISC;
    float* sB1 = sMi + MI_B1;
    float* sB2 = sMi + MI_B2;
    float* sB3 = sMi + MI_B3;
    float* sW4 = sMi + MI_W4;
    float* sBg = sMi + MI_BG;
    float* sPart = sMi + MI_PART;

    const int tid  = threadIdx.x;
    const int wid  = tid >> 5;
    const int lane = tid & 31;

    const int grp  = wid >> 2;
    const int gw   = wid & 3;
    const int gtid = tid & 127;
    const int mslot = gw >> 1;
    const int nslot = gw & 1;
    const int gg = lane >> 2;
    const int t  = lane & 3;

    const uint32_t sAu  = smem_u32(sA);
    const uint32_t sW1u = smem_u32(sW1);
    const uint32_t sW3u = smem_u32(sW3);

    const int arow = grp * 64 + mslot * 32 + (lane & 15);
    const int acol = (lane >> 4) << 2;
    const uint32_t aBase0 = sAu + (uint32_t)(((arow)      * A_STRIDE + acol) << 2);
    const uint32_t aBase1 = sAu + (uint32_t)(((arow + 16) * A_STRIDE + acol) << 2);
    const int nrow = nslot * 32 + ((lane & 16) >> 1) + (lane & 7);
    const int ncol = (lane & 8) ? 4 : 0;
    const uint32_t b1Base0 = sW1u + (uint32_t)((nrow * W1_STRIDE + ncol) << 2);
    const uint32_t b1Base1 = b1Base0 + (uint32_t)(16 * W1_STRIDE * 4);
    const uint32_t w3Base0 = sW3u + (uint32_t)((nrow * WST + ncol) << 2);
    const uint32_t w3Base1 = w3Base0 + (uint32_t)(16 * WST * 4);

    // ---- one-time init ----
    {
        const float4* s = (const float4*)g_W1T;
        float4* d = (float4*)sW1;
        for (int i = tid; i < 64 * W1_STRIDE / 4; i += NTHREADS) d[i] = s[i];
    }
    for (int i = tid; i < 64 * 64; i += NTHREADS) {
        int n = i >> 6, k = i & 63;
        sA[n * WST + k]  = g_W2Tc[i];     // temp stage for W2 hoist
        sW3[n * WST + k] = g_W3Tc[i];     // persistent W3 image
    }
    if (tid < 64) {
        sB1[tid] = b1[tid]; sB2[tid] = b2[tid]; sB3[tid] = b3[tid];
        sW4[tid] = W4[tid];
    }
    if (tid < 96) ((float2*)sBg)[tid] = ((const float2*)Bg)[tid];
    const float b4v = b4[0];
    __syncthreads();

    // hoist W2 B-fragments to registers
    uint32_t B2f[64];
    {
        const uint32_t wBase0 = sAu + (uint32_t)((nrow * WST + ncol) << 2);
        const uint32_t wBase1 = wBase0 + (uint32_t)(16 * WST * 4);
#pragma unroll
        for (int kk = 0; kk < 8; ++kk) {
            ldsm4(B2f + kk * 8,     wBase0 + kk * 32);
            ldsm4(B2f + kk * 8 + 4, wBase1 + kk * 32);
        }
    }
    __syncthreads();

    for (int tile = blockIdx.x; tile < NTILES; tile += GRID_CTAS) {
        const int p0 = tile * TILE_PTS;
        const int b  = p0 >> 16;

        // ---- warp-local projection: lanes 0..15 own this warp's 16 points ----
        float fx = 0.f, fy = 0.f, va = 0.f, ppx = 0.f, ppy = 0.f, ppz = 0.f;
        int x0 = -100000, y0 = -100000;
        {
            const int q0 = grp * 64 + gw * 16;
            if (lane < 16) {
                const float* pt = points + (size_t)(p0 + q0 + lane) * 3;
                ppx = pt[0]; ppy = pt[1]; ppz = pt[2];
                const float* R = rtm + b * 12;
                const float* K = kmat + b * 9;
                const float cx = fmaf(R[0], ppx, fmaf(R[1], ppy, fmaf(R[2],  ppz, R[3])));
                const float cy = fmaf(R[4], ppx, fmaf(R[5], ppy, fmaf(R[6],  ppz, R[7])));
                const float cz = fmaf(R[8], ppx, fmaf(R[9], ppy, fmaf(R[10], ppz, R[11])));
                const float ix = fmaf(K[0], cx, fmaf(K[1], cy, K[2] * cz));
                const float iy = fmaf(K[3], cx, fmaf(K[4], cy, K[5] * cz));
                const float iz = fmaf(K[6], cx, fmaf(K[7], cy, K[8] * cz));
                const bool pos = (iz > 0.0f);
                const float zz = iz + 1e-8f;
                const float u = __fdividef(ix, zz), v = __fdividef(iy, zz);
                const float xf = floorf(u), yf = floorf(v);
                fx = u - xf; fy = v - yf;
                x0 = (int)xf; y0 = (int)yf;
                if (!pos) { x0 = -100000; y0 = -100000; fx = 0.f; fy = 0.f; }
                va = pos ? 1.0f : 0.0f;
            }
        }

        // ---- merged gather + Fourier (Fourier MUFU fills LDG latency) ----
        {
            const int q0 = grp * 64 + gw * 16;
            const float* baseb = g_tf + (size_t)b * 3136 * CHN + lane * 4;
            const float TWOPI = 6.283185307179586f;
            const float bx0 = sBg[lane * 3],        by0 = sBg[lane * 3 + 1],        bz0 = sBg[lane * 3 + 2];
            const float bx1 = sBg[(lane + 32) * 3], by1 = sBg[(lane + 32) * 3 + 1], bz1 = sBg[(lane + 32) * 3 + 2];
#pragma unroll 4
            for (int i = 0; i < 16; ++i) {
                const int q = q0 + i;
                const float gfx = __shfl_sync(0xffffffffu, fx, i);
                const float gfy = __shfl_sync(0xffffffffu, fy, i);
                const float gv  = __shfl_sync(0xffffffffu, va, i);
                const int   gx  = __shfl_sync(0xffffffffu, x0, i);
                const int   gy  = __shfl_sync(0xffffffffu, y0, i);
                const float qx  = __shfl_sync(0xffffffffu, ppx, i);
                const float qy  = __shfl_sync(0xffffffffu, ppy, i);
                const float qz  = __shfl_sync(0xffffffffu, ppz, i);

                const float ax = 1.0f - gfx, ay = 1.0f - gfy;
                const float w00 = ax * ay * gv;
                const float w10 = gfx * ay * gv;
                const float w01 = ax * gfy * gv;
                const float w11 = gfx * gfy * gv;
                const bool x0in = (gx >= 0) && (gx < WW);
                const bool x1in = (gx >= -1) && (gx < WW - 1);
                const bool y0in = (gy >= 0) && (gy < HH);
                const bool y1in = (gy >= -1) && (gy < HH - 1);
                const int rowoff = (gy * WW + gx) * CHN;
                float4 acc4 = make_float4(0.f, 0.f, 0.f, 0.f);
                if (x0in && y0in) {
                    float4 v4 = *(const float4*)(baseb + rowoff);
                    acc4.x = fmaf(w00, v4.x, acc4.x); acc4.y = fmaf(w00, v4.y, acc4.y);
                    acc4.z = fmaf(w00, v4.z, acc4.z); acc4.w = fmaf(w00, v4.w, acc4.w);
                }
                if (x1in && y0in) {
                    float4 v4 = *(const float4*)(baseb + rowoff + CHN);
                    acc4.x = fmaf(w10, v4.x, acc4.x); acc4.y = fmaf(w10, v4.y, acc4.y);
                    acc4.z = fmaf(w10, v4.z, acc4.z); acc4.w = fmaf(w10, v4.w, acc4.w);
                }
                if (x0in && y1in) {
                    float4 v4 = *(const float4*)(baseb + rowoff + WW * CHN);
                    acc4.x = fmaf(w01, v4.x, acc4.x); acc4.y = fmaf(w01, v4.y, acc4.y);
                    acc4.z = fmaf(w01, v4.z, acc4.z); acc4.w = fmaf(w01, v4.w, acc4.w);
                }
                if (x1in && y1in) {
                    float4 v4 = *(const float4*)(baseb + rowoff + (WW + 1) * CHN);
                    acc4.x = fmaf(w11, v4.x, acc4.x); acc4.y = fmaf(w11, v4.y, acc4.y);
                    acc4.z = fmaf(w11, v4.z, acc4.z); acc4.w = fmaf(w11, v4.w, acc4.w);
                }

                // Fourier for this point (overlaps with the loads above)
                const float xp0 = TWOPI * fmaf(qx, bx0, fmaf(qy, by0, qz * bz0));
                const float xp1 = TWOPI * fmaf(qx, bx1, fmaf(qy, by1, qz * bz1));
                float* row = sA + q * A_STRIDE;
                row[128 + lane]      = to_tf32(__sinf(xp0));
                row[128 + lane + 32] = to_tf32(__sinf(xp1));
                row[192 + lane]      = to_tf32(__cosf(xp0));
                row[192 + lane + 32] = to_tf32(__cosf(xp1));

                acc4.x = to_tf32(acc4.x); acc4.y = to_tf32(acc4.y);
                acc4.z = to_tf32(acc4.z); acc4.w = to_tf32(acc4.w);
                *(float4*)(row + lane * 4) = acc4;
            }
        }
        GBAR(grp);   // group's A half fully built

        // ================= Layer 1 (pipelined): [64x256] @ W1 =================
        float acc[2][4][4];
#pragma unroll
        for (int mt = 0; mt < 2; ++mt)
#pragma unroll
            for (int nt = 0; nt < 4; ++nt)
#pragma unroll
                for (int j = 0; j < 4; ++j) acc[mt][nt][j] = 0.0f;
        {
            uint32_t aa0[2][4], aa1[2][4], BB[2][8];
            ldsm4(aa0[0], aBase0);
            ldsm4(aa1[0], aBase1);
            ldsm4(BB[0],     b1Base0);
            ldsm4(BB[0] + 4, b1Base1);
#pragma unroll 2
            for (int kb = 0; kb < 16; ++kb) {
                const int k1 = 2 * kb + 1;
                ldsm4(aa0[1], aBase0 + k1 * 32);
                ldsm4(aa1[1], aBase1 + k1 * 32);
                ldsm4(BB[1],     b1Base0 + k1 * 32);
                ldsm4(BB[1] + 4, b1Base1 + k1 * 32);
#pragma unroll
                for (int nt = 0; nt < 4; ++nt) {
                    mma16n8k8(acc[0][nt], aa0[0], BB[0][nt * 2], BB[0][nt * 2 + 1]);
                    mma16n8k8(acc[1][nt], aa1[0], BB[0][nt * 2], BB[0][nt * 2 + 1]);
                }
                if (kb < 15) {
                    ldsm4(aa0[0], aBase0 + (k1 + 1) * 32);
                    ldsm4(aa1[0], aBase1 + (k1 + 1) * 32);
                    ldsm4(BB[0],     b1Base0 + (k1 + 1) * 32);
                    ldsm4(BB[0] + 4, b1Base1 + (k1 + 1) * 32);
                }
#pragma unroll
                for (int nt = 0; nt < 4; ++nt) {
                    mma16n8k8(acc[0][nt], aa0[1], BB[1][nt * 2], BB[1][nt * 2 + 1]);
                    mma16n8k8(acc[1][nt], aa1[1], BB[1][nt * 2], BB[1][nt * 2 + 1]);
                }
            }
        }
        GBAR(grp);   // group's L1 A-reads done

        // relu(acc + b1) -> A cols [0,64)
#pragma unroll
        for (int mt = 0; mt < 2; ++mt) {
            const int r0 = grp * 64 + mslot * 32 + mt * 16 + gg;
#pragma unroll
            for (int nt = 0; nt < 4; ++nt) {
                const int col = nslot * 32 + nt * 8 + t * 2;
                float2 v0, v1;
                v0.x = to_tf32(fmaxf(acc[mt][nt][0] + sB1[col], 0.f));
                v0.y = to_tf32(fmaxf(acc[mt][nt][1] + sB1[col + 1], 0.f));
                v1.x = to_tf32(fmaxf(acc[mt][nt][2] + sB1[col], 0.f));
                v1.y = to_tf32(fmaxf(acc[mt][nt][3] + sB1[col + 1], 0.f));
                *(float2*)(sA + r0 * A_STRIDE + col) = v0;
                *(float2*)(sA + (r0 + 8) * A_STRIDE + col) = v1;
            }
        }
        GBAR(grp);   // h1 ready

        // ================= Layer 2 (pipelined A): h1 @ W2, B in regs =========
#pragma unroll
        for (int mt = 0; mt < 2; ++mt)
#pragma unroll
            for (int nt = 0; nt < 4; ++nt)
#pragma unroll
                for (int j = 0; j < 4; ++j) acc[mt][nt][j] = 0.0f;
        {
            uint32_t aa0[2][4], aa1[2][4];
            ldsm4(aa0[0], aBase0);
            ldsm4(aa1[0], aBase1);
#pragma unroll
            for (int kb = 0; kb < 4; ++kb) {
                const int k1 = 2 * kb + 1;
                ldsm4(aa0[1], aBase0 + k1 * 32);
                ldsm4(aa1[1], aBase1 + k1 * 32);
#pragma unroll
                for (int nt = 0; nt < 4; ++nt) {
                    mma16n8k8(acc[0][nt], aa0[0], B2f[(k1 - 1) * 8 + nt * 2], B2f[(k1 - 1) * 8 + nt * 2 + 1]);
                    mma16n8k8(acc[1][nt], aa1[0], B2f[(k1 - 1) * 8 + nt * 2], B2f[(k1 - 1) * 8 + nt * 2 + 1]);
                }
                if (kb < 3) {
                    ldsm4(aa0[0], aBase0 + (k1 + 1) * 32);
                    ldsm4(aa1[0], aBase1 + (k1 + 1) * 32);
                }
#pragma unroll
                for (int nt = 0; nt < 4; ++nt) {
                    mma16n8k8(acc[0][nt], aa0[1], B2f[k1 * 8 + nt * 2], B2f[k1 * 8 + nt * 2 + 1]);
                    mma16n8k8(acc[1][nt], aa1[1], B2f[k1 * 8 + nt * 2], B2f[k1 * 8 + nt * 2 + 1]);
                }
            }
        }
        // relu(acc + b2) -> A cols [64,128)  (disjoint from h1 reads)
#pragma unroll
        for (int mt = 0; mt < 2; ++mt) {
            const int r0 = grp * 64 + mslot * 32 + mt * 16 + gg;
#pragma unroll
            for (int nt = 0; nt < 4; ++nt) {
                const int col = nslot * 32 + nt * 8 + t * 2;
                float2 v0, v1;
                v0.x = to_tf32(fmaxf(acc[mt][nt][0] + sB2[col], 0.f));
                v0.y = to_tf32(fmaxf(acc[mt][nt][1] + sB2[col + 1], 0.f));
                v1.x = to_tf32(fmaxf(acc[mt][nt][2] + sB2[col], 0.f));
                v1.y = to_tf32(fmaxf(acc[mt][nt][3] + sB2[col + 1], 0.f));
                *(float2*)(sA + r0 * A_STRIDE + 64 + col) = v0;
                *(float2*)(sA + (r0 + 8) * A_STRIDE + 64 + col) = v1;
            }
        }
        GBAR(grp);   // h2 ready

        // ================= Layer 3 (pipelined): h2 @ W3 from smem ============
#pragma unroll
        for (int mt = 0; mt < 2; ++mt)
#pragma unroll
            for (int nt = 0; nt < 4; ++nt)
#pragma unroll
                for (int j = 0; j < 4; ++j) acc[mt][nt][j] = 0.0f;
        {
            uint32_t aa0[2][4], aa1[2][4], BB[2][8];
            ldsm4(aa0[0], aBase0 + 256);
            ldsm4(aa1[0], aBase1 + 256);
            ldsm4(BB[0],     w3Base0);
            ldsm4(BB[0] + 4, w3Base1);
#pragma unroll
            for (int kb = 0; kb < 4; ++kb) {
                const int k1 = 2 * kb + 1;
                ldsm4(aa0[1], aBase0 + 256 + k1 * 32);
                ldsm4(aa1[1], aBase1 + 256 + k1 * 32);
                ldsm4(BB[1],     w3Base0 + k1 * 32);
                ldsm4(BB[1] + 4, w3Base1 + k1 * 32);
#pragma unroll
                for (int nt = 0; nt < 4; ++nt) {
                    mma16n8k8(acc[0][nt], aa0[0], BB[0][nt * 2], BB[0][nt * 2 + 1]);
                    mma16n8k8(acc[1][nt], aa1[0], BB[0][nt * 2], BB[0][nt * 2 + 1]);
                }
                if (kb < 3) {
                    ldsm4(aa0[0], aBase0 + 256 + (k1 + 1) * 32);
                    ldsm4(aa1[0], aBase1 + 256 + (k1 + 1) * 32);
                    ldsm4(BB[0],     w3Base0 + (k1 + 1) * 32);
                    ldsm4(BB[0] + 4, w3Base1 + (k1 + 1) * 32);
                }
#pragma unroll
                for (int nt = 0; nt < 4; ++nt) {
                    mma16n8k8(acc[0][nt], aa0[1], BB[1][nt * 2], BB[1][nt * 2 + 1]);
                    mma16n8k8(acc[1][nt], aa1[1], BB[1][nt * 2], BB[1][nt * 2 + 1]);
                }
            }
        }

        // ---- layer 4 epilogue ----
        {
            float pr[2][2];
            pr[0][0] = pr[0][1] = pr[1][0] = pr[1][1] = 0.0f;
#pragma unroll
            for (int mt = 0; mt < 2; ++mt)
#pragma unroll
                for (int nt = 0; nt < 4; ++nt) {
                    const int col = nslot * 32 + nt * 8 + t * 2;
                    pr[mt][0] = fmaf(fmaxf(acc[mt][nt][0] + sB3[col], 0.f),     sW4[col],     pr[mt][0]);
                    pr[mt][0] = fmaf(fmaxf(acc[mt][nt][1] + sB3[col + 1], 0.f), sW4[col + 1], pr[mt][0]);
                    pr[mt][1] = fmaf(fmaxf(acc[mt][nt][2] + sB3[col], 0.f),     sW4[col],     pr[mt][1]);
                    pr[mt][1] = fmaf(fmaxf(acc[mt][nt][3] + sB3[col + 1], 0.f), sW4[col + 1], pr[mt][1]);
                }
#pragma unroll
            for (int mt = 0; mt < 2; ++mt) {
                pr[mt][0] += __shfl_xor_sync(0xffffffffu, pr[mt][0], 1);
                pr[mt][0] += __shfl_xor_sync(0xffffffffu, pr[mt][0], 2);
                pr[mt][1] += __shfl_xor_sync(0xffffffffu, pr[mt][1], 1);
                pr[mt][1] += __shfl_xor_sync(0xffffffffu, pr[mt][1], 2);
                if (t == 0) {
                    const int lr = mslot * 32 + mt * 16 + gg;
                    sPart[grp * 128 + nslot * 64 + lr] = pr[mt][0];
                    sPart[grp * 128 + nslot * 64 + lr + 8] = pr[mt][1];
                }
            }
        }
        GBAR(grp);   // sPart half ready; group's L3 A-reads done
        if (gtid < 64)
            out[p0 + grp * 64 + gtid] =
                sPart[grp * 128 + gtid] + sPart[grp * 128 + 64 + gtid] + b4v;
    }
}

// ---------------------------------------------------------------------------
// Launch
// ---------------------------------------------------------------------------
extern "C" void kernel_launch(void* const* d_in, const int* in_sizes, int n_in,
                              void* d_out, int out_size) {
    const float* features = (const float*)d_in[0];
    const float* points   = (const float*)d_in[1];
    const float* kmat     = (const float*)d_in[2];
    const float* rtm      = (const float*)d_in[3];
    const float* Bg       = (const float*)d_in[4];
    const float* W1 = (const float*)d_in[5];
    const float* b1 = (const float*)d_in[6];
    const float* W2 = (const float*)d_in[7];
    const float* b2 = (const float*)d_in[8];
    const float* W3 = (const float*)d_in[9];
    const float* b3 = (const float*)d_in[10];
    const float* W4 = (const float*)d_in[11];
    const float* b4 = (const float*)d_in[12];

    dim3 tb(32, 32);
    dim3 tg(3136 / 32, CHN / 32, BATCH);
    transpose_kernel<<<tg, tb>>>(features, W1, W2, W3);

    cudaFuncSetAttribute(decoder_kernel,
                         cudaFuncAttributeMaxDynamicSharedMemorySize, SMEM_TOTAL);
    decoder_kernel<<<GRID_CTAS, NTHREADS, SMEM_TOTAL>>>(
        points, kmat, rtm, Bg, b1, b2, b3, W4, b4, (float*)d_out);
}